// round 4
// baseline (speedup 1.0000x reference)
#include <cuda_runtime.h>
#include <math.h>

#define NEG_SLOPE 0.01f
#define MAXN 100000
#define EMAX 3200000
#define NB_MAX 128
#define HID 64
#define INC 128
#define OUTC 5

typedef unsigned long long ull;

// ---------------- scratch (device globals; no allocation allowed) ----------------
__device__ int   g_w8;                        // 1 if indices are int64, 0 if int32
__device__ int   g_cnt [MAXN];                // in-degree counts
__device__ int   g_bsum[NB_MAX];              // block sums for scan
__device__ int   g_off [MAXN + 1];            // CSR row offsets
__device__ int   g_pos [MAXN];                // fill cursors
__device__ __align__(16) int2 g_edge[EMAX];   // (src, coef) sorted by dst
__device__ float g_dinv[MAXN];
__device__ __align__(256) float g_h   [(size_t)MAXN * HID];
__device__ __align__(256) float g_agg [(size_t)MAXN * HID];
__device__ __align__(256) float g_h1  [(size_t)MAXN * HID];
__device__ __align__(256) float g_agg1[(size_t)MAXN * HID];

// ---------------- helpers ----------------
__device__ __forceinline__ int ldidx(const void* p, long long i, int w8) {
    return w8 ? (int)__ldg((const long long*)p + i) : __ldg((const int*)p + i);
}
__device__ __forceinline__ float leaky(float v) { return v > 0.f ? v : NEG_SLOPE * v; }

#define FFMA2(d, a, b, c) \
    asm("fma.rn.f32x2 %0, %1, %2, %3;" : "=l"(d) : "l"(a), "l"(b), "l"(c))
#define MULX2(d, a, b) \
    asm("mul.rn.f32x2 %0, %1, %2;" : "=l"(d) : "l"(a), "l"(b))
#define PACK2(d, lo, hi) \
    asm("mov.b64 %0, {%1, %2};" : "=l"(d) : "f"(lo), "f"(hi))

// ---------------- fused detect + zero counts ----------------
__global__ void prep_kernel(const unsigned int* p, int n) {
    int i = blockIdx.x * blockDim.x + threadIdx.x;
    if (i < n) g_cnt[i] = 0;
    if (blockIdx.x == 0) {
        __shared__ int nz;
        if (threadIdx.x == 0) nz = 0;
        __syncthreads();
        if (p[2 * threadIdx.x + 1] != 0u) atomicExch(&nz, 1);
        __syncthreads();
        if (threadIdx.x == 0) g_w8 = (nz == 0) ? 1 : 0;
    }
}

__global__ void count_kernel(const void* ei, int e32) {
    int w8 = g_w8;
    long long E = w8 ? (e32 >> 1) : e32;
    long long e = (long long)blockIdx.x * blockDim.x + threadIdx.x;
    if (e >= E) return;
    int d = ldidx(ei, E + e, w8);
    atomicAdd(&g_cnt[d], 1);
}

// ---------------- scan (block sums + dinv fused) ----------------
__global__ void scanA_kernel(int n) {           // grid nb, block 1024
    __shared__ int sh[1024];
    int i = blockIdx.x * 1024 + threadIdx.x;
    int v = (i < n) ? g_cnt[i] : 0;
    if (i < n) g_dinv[i] = rsqrtf((float)v + 1.0f);   // +1 self loop
    sh[threadIdx.x] = v;
    __syncthreads();
    for (int s = 512; s > 0; s >>= 1) {
        if (threadIdx.x < s) sh[threadIdx.x] += sh[threadIdx.x + s];
        __syncthreads();
    }
    if (threadIdx.x == 0) g_bsum[blockIdx.x] = sh[0];
}

__global__ void scanB_kernel(int nb) {          // 1 block, NB_MAX threads
    __shared__ int sh[NB_MAX];
    int t = threadIdx.x;
    int v0 = (t < nb) ? g_bsum[t] : 0;
    sh[t] = v0;
    __syncthreads();
    for (int o = 1; o < NB_MAX; o <<= 1) {
        int u = (t >= o) ? sh[t - o] : 0;
        __syncthreads();
        sh[t] += u;
        __syncthreads();
    }
    if (t < nb) g_bsum[t] = sh[t] - v0;         // exclusive
}

__global__ void scanC_kernel(int n) {           // grid nb, block 1024
    __shared__ int sh[1024];
    int b = blockIdx.x, t = threadIdx.x;
    int i = b * 1024 + t;
    int v = (i < n) ? g_cnt[i] : 0;
    sh[t] = v;
    __syncthreads();
    for (int o = 1; o < 1024; o <<= 1) {
        int u = (t >= o) ? sh[t - o] : 0;
        __syncthreads();
        sh[t] += u;
        __syncthreads();
    }
    int base = g_bsum[b];
    if (i < n) {
        int off = base + sh[t] - v;             // exclusive
        g_off[i] = off;
        g_pos[i] = off;
        if (i == n - 1) g_off[n] = base + sh[t];
    }
}

__global__ void fill_kernel(const void* ei, int e32) {
    int w8 = g_w8;
    long long E = w8 ? (e32 >> 1) : e32;
    long long e = (long long)blockIdx.x * blockDim.x + threadIdx.x;
    if (e >= E) return;
    int s = ldidx(ei, e, w8);
    int d = ldidx(ei, E + e, w8);
    float c = __ldg(&g_dinv[s]) * __ldg(&g_dinv[d]);
    int p = atomicAdd(&g_pos[d], 1);
    if (p < EMAX) g_edge[p] = make_int2(s, __float_as_int(c));
}

// ---------------- fused GEMM (f32x2 packed FMA) ----------------
// LAYER==1: H = X @ W0            -> g_h
// LAYER==2: A = leaky(g_agg + b0) ; H = A @ W1 -> g_h1
template<int K, int LAYER>
__global__ void gemm_kernel(const float* __restrict__ Xext,
                            const float* __restrict__ W,
                            const float* __restrict__ bias,
                            int n)
{
    const int CK = 32;
    __shared__ __align__(16) float Xs2[64][2 * CK];   // duplicated pairs (v,v)
    __shared__ __align__(16) float Ws[CK][64];

    int tid = threadIdx.x;
    int tx = tid & 15;
    int ty = tid >> 4;
    int rb = blockIdx.x * 64;

    ull acc[4][2] = {};

    for (int kc = 0; kc < K; kc += CK) {
        for (int i = tid; i < 64 * CK; i += 256) {
            int r = i >> 5, c = i & 31;
            int row = rb + r;
            float v = 0.f;
            if (row < n) {
                if (LAYER == 1) {
                    v = Xext[(long long)row * K + kc + c];
                } else {
                    v = leaky(g_agg[(long long)row * K + kc + c] + bias[kc + c]);
                }
            }
            float2 vv = make_float2(v, v);
            *(float2*)&Xs2[r][2 * c] = vv;
        }
        for (int i = tid; i < CK * 64; i += 256) {
            int k = i >> 6, c = i & 63;
            Ws[k][c] = W[(long long)(kc + k) * 64 + c];
        }
        __syncthreads();

        #pragma unroll
        for (int kk = 0; kk < CK; kk++) {
            ulonglong2 wv = *(const ulonglong2*)&Ws[kk][tx * 4];
            #pragma unroll
            for (int i = 0; i < 4; i++) {
                ull xx = *(const ull*)&Xs2[ty * 4 + i][2 * kk];
                FFMA2(acc[i][0], xx, wv.x, acc[i][0]);
                FFMA2(acc[i][1], xx, wv.y, acc[i][1]);
            }
        }
        __syncthreads();
    }

    float* H = (LAYER == 1) ? g_h : g_h1;
    #pragma unroll
    for (int i = 0; i < 4; i++) {
        int row = rb + ty * 4 + i;
        if (row >= n) break;
        ulonglong2 hv;
        hv.x = acc[i][0];
        hv.y = acc[i][1];
        *(ulonglong2*)&H[(long long)row * 64 + tx * 4] = hv;
    }
}

// ---------------- CSR pull aggregation: one warp per dst row ----------------
// AGG[d] = dinv[d]^2 * H[d] + sum_e coef[e] * H[src[e]]
template<int LAYER>
__global__ void agg_kernel(int n)
{
    int row  = (blockIdx.x * blockDim.x + threadIdx.x) >> 5;
    int lane = threadIdx.x & 31;
    if (row >= n) return;

    const float* __restrict__ H = (LAYER == 1) ? g_h : g_h1;
    float* __restrict__ AGG     = (LAYER == 1) ? g_agg : g_agg1;

    float dd = g_dinv[row];
    ull hv = *(const ull*)(H + (size_t)row * 64 + lane * 2);
    ull d2p; PACK2(d2p, dd * dd, dd * dd);
    ull acc; MULX2(acc, hv, d2p);

    int beg = g_off[row], end = g_off[row + 1];
    for (int b = beg; b < end; b += 32) {
        int e = b + lane;
        int s = 0; float c = 0.f;
        if (e < end) {
            int2 sc = __ldg(&g_edge[e]);
            s = sc.x;
            c = __int_as_float(sc.y);
        }
        int cnt = end - b; if (cnt > 32) cnt = 32;
        int j = 0;
        for (; j + 4 <= cnt; j += 4) {
            int s0 = __shfl_sync(0xFFFFFFFFu, s, j);
            int s1 = __shfl_sync(0xFFFFFFFFu, s, j + 1);
            int s2 = __shfl_sync(0xFFFFFFFFu, s, j + 2);
            int s3 = __shfl_sync(0xFFFFFFFFu, s, j + 3);
            float c0 = __shfl_sync(0xFFFFFFFFu, c, j);
            float c1 = __shfl_sync(0xFFFFFFFFu, c, j + 1);
            float c2 = __shfl_sync(0xFFFFFFFFu, c, j + 2);
            float c3 = __shfl_sync(0xFFFFFFFFu, c, j + 3);
            ull v0 = *(const ull*)(H + (size_t)s0 * 64 + lane * 2);
            ull v1 = *(const ull*)(H + (size_t)s1 * 64 + lane * 2);
            ull v2 = *(const ull*)(H + (size_t)s2 * 64 + lane * 2);
            ull v3 = *(const ull*)(H + (size_t)s3 * 64 + lane * 2);
            ull p0, p1, p2, p3;
            PACK2(p0, c0, c0); PACK2(p1, c1, c1);
            PACK2(p2, c2, c2); PACK2(p3, c3, c3);
            FFMA2(acc, v0, p0, acc);
            FFMA2(acc, v1, p1, acc);
            FFMA2(acc, v2, p2, acc);
            FFMA2(acc, v3, p3, acc);
        }
        for (; j < cnt; j++) {
            int sj = __shfl_sync(0xFFFFFFFFu, s, j);
            float cj = __shfl_sync(0xFFFFFFFFu, c, j);
            ull vj = *(const ull*)(H + (size_t)sj * 64 + lane * 2);
            ull pj; PACK2(pj, cj, cj);
            FFMA2(acc, vj, pj, acc);
        }
    }
    *(ull*)(AGG + (size_t)row * 64 + lane * 2) = acc;
}

// ---------------- final: select rows, activation, tiny MLP + sigmoid ----------------
__global__ void final_kernel(const void* idxp, int nsel,
                             const float* __restrict__ b1,
                             const float* __restrict__ Wm,
                             const float* __restrict__ bm,
                             float* __restrict__ out_hsel,
                             float* __restrict__ out_prob)
{
    int w8 = g_w8;
    int warp = (blockIdx.x * blockDim.x + threadIdx.x) >> 5;
    int lane = threadIdx.x & 31;
    if (warp >= nsel) return;

    int v = ldidx(idxp, warp, w8);
    float a0 = leaky(g_agg1[(long long)v * 64 + lane]      + __ldg(&b1[lane]));
    float a1 = leaky(g_agg1[(long long)v * 64 + lane + 32] + __ldg(&b1[lane + 32]));
    out_hsel[(long long)warp * 64 + lane]      = a0;
    out_hsel[(long long)warp * 64 + lane + 32] = a1;

    #pragma unroll
    for (int j = 0; j < OUTC; j++) {
        float p = a0 * __ldg(&Wm[lane * OUTC + j]) + a1 * __ldg(&Wm[(lane + 32) * OUTC + j]);
        #pragma unroll
        for (int off = 16; off > 0; off >>= 1)
            p += __shfl_down_sync(0xFFFFFFFFu, p, off);
        if (lane == 0)
            out_prob[(long long)warp * OUTC + j] = 1.0f / (1.0f + expf(-(p + __ldg(&bm[j]))));
    }
}

// ---------------- launch ----------------
extern "C" void kernel_launch(void* const* d_in, const int* in_sizes, int n_in,
                              void* d_out, int out_size)
{
    const float* x   = (const float*)d_in[0];
    const void*  ei  = d_in[1];
    const void*  idx = d_in[2];
    const float* W0  = (const float*)d_in[3];
    const float* b0  = (const float*)d_in[4];
    const float* W1  = (const float*)d_in[5];
    const float* b1  = (const float*)d_in[6];
    const float* Wm  = (const float*)d_in[7];
    const float* bm  = (const float*)d_in[8];

    int n = in_sizes[0] / INC;
    if (n > MAXN) n = MAXN;
    int e32 = in_sizes[1] / 2;                  // edge count if int32
    int nsel = out_size / (HID + OUTC);

    float* out_hsel = (float*)d_out;
    float* out_prob = (float*)d_out + (size_t)nsel * HID;

    int nb = (n + 1023) / 1024;                 // <= NB_MAX for n<=100k

    // lazy-init side stream + events (host resources only; reused every call,
    // identical work each call)
    static cudaStream_t s_side = nullptr;
    static cudaEvent_t  e_fork = nullptr, e_join = nullptr;
    if (!s_side) {
        cudaStreamCreateWithFlags(&s_side, cudaStreamNonBlocking);
        cudaEventCreateWithFlags(&e_fork, cudaEventDisableTiming);
        cudaEventCreateWithFlags(&e_join, cudaEventDisableTiming);
    }

    // fork: side stream builds CSR while main stream runs GEMM layer 1
    cudaEventRecord(e_fork, 0);
    cudaStreamWaitEvent(s_side, e_fork, 0);

    prep_kernel <<<(n + 511) / 512, 512, 0, s_side>>>((const unsigned int*)ei, n);
    count_kernel<<<(e32 + 255) / 256, 256, 0, s_side>>>(ei, e32);
    scanA_kernel<<<nb, 1024, 0, s_side>>>(n);
    scanB_kernel<<<1, NB_MAX, 0, s_side>>>(nb);
    scanC_kernel<<<nb, 1024, 0, s_side>>>(n);
    fill_kernel <<<(e32 + 255) / 256, 256, 0, s_side>>>(ei, e32);
    cudaEventRecord(e_join, s_side);

    int gblocks = (n + 63) / 64;
    int ablocks = (int)(((long long)n * 32 + 255) / 256);

    gemm_kernel<INC, 1><<<gblocks, 256>>>(x, W0, nullptr, n);

    // join: aggregation needs both H (main) and CSR+dinv (side)
    cudaStreamWaitEvent(0, e_join, 0);

    agg_kernel<1><<<ablocks, 256>>>(n);
    gemm_kernel<HID, 2><<<gblocks, 256>>>(nullptr, W1, b0, n);
    agg_kernel<2><<<ablocks, 256>>>(n);

    final_kernel<<<(nsel * 32 + 255) / 256, 256>>>(idx, nsel, b1, Wm, bm,
                                                   out_hsel, out_prob);
}